// round 17
// baseline (speedup 1.0000x reference)
#include <cuda_runtime.h>
#include <cstdint>

#define N_NODES 100000
#define N_EDGES 1000000
#define D 64
#define CAP 64           // padded CSR slots/node (Poisson(10): P(deg>64)~1e-30; fallback exists)

// Scratch (device globals — no allocations allowed).
// g_cnt starts zeroed (BSS) and is re-zeroed by gather_kernel each run.
__device__ __align__(16) float g_mean[N_NODES * D];
__device__ int g_cnt[N_NODES];
__device__ __align__(16) int g_csr[N_NODES * CAP];

// ---------------------------------------------------------------------------
// Kernel 1: CSR fill. 4 independent edges per thread (strided quarters):
// coalesced loads, 4 overlapping atomic chains (fill is atomic-latency bound:
// measured occ 79.6% / issue 4.6% at 1 edge/thread).
// ---------------------------------------------------------------------------
#define EQ (N_EDGES / 4)

__global__ __launch_bounds__(256) void fill_kernel(const int* __restrict__ ei) {
    const int t = blockIdx.x * 256 + threadIdx.x;
    if (t >= EQ) return;
    int src[4], dst[4];
    #pragma unroll
    for (int q = 0; q < 4; q++) {
        const int e = t + q * EQ;
        src[q] = __ldg(ei + e);
        dst[q] = __ldg(ei + N_EDGES + e);
    }
    #pragma unroll
    for (int q = 0; q < 4; q++) {
        const int pos = atomicAdd(g_cnt + dst[q], 1);
        if (pos < CAP) g_csr[dst[q] * CAP + pos] = src[q];
    }
}

// ---------------------------------------------------------------------------
// Kernel 2: gather (round-5 form). Half-warp per node, LDG.128 streams,
// register accumulation, single mean-row write. Resets g_cnt for next run.
// ---------------------------------------------------------------------------
__global__ __launch_bounds__(256) void gather_kernel(const float* __restrict__ x,
                                                     const int* __restrict__ ei) {
    const int warp = blockIdx.x * 8 + (threadIdx.x >> 5);
    const int lane = threadIdx.x & 31;
    const int sub  = lane >> 4;
    const int j    = lane & 15;
    const int node = warp * 2 + sub;      // grid covers exactly N_NODES

    const int cnt  = g_cnt[node];
    if (j == 0) g_cnt[node] = 0;          // restore invariant for next replay
    const float r  = 1.0f / (float)(cnt > 1 ? cnt : 1);
    const float4* x4 = reinterpret_cast<const float4*>(x);

    float4 acc = make_float4(0.f, 0.f, 0.f, 0.f);
    if (cnt <= CAP) {
        const int4* row = reinterpret_cast<const int4*>(g_csr + node * CAP);
        for (int e0 = 0; e0 < cnt; e0 += 4) {
            const int4 s = __ldg(row + (e0 >> 2));   // broadcast in half-warp
            const int rem = cnt - e0;
            float4 v0 = __ldg(x4 + (size_t)s.x * 16 + j);
            float4 v1, v2, v3;
            if (rem > 1) v1 = __ldg(x4 + (size_t)s.y * 16 + j);
            if (rem > 2) v2 = __ldg(x4 + (size_t)s.z * 16 + j);
            if (rem > 3) v3 = __ldg(x4 + (size_t)s.w * 16 + j);
            acc.x += v0.x; acc.y += v0.y; acc.z += v0.z; acc.w += v0.w;
            if (rem > 1) { acc.x += v1.x; acc.y += v1.y; acc.z += v1.z; acc.w += v1.w; }
            if (rem > 2) { acc.x += v2.x; acc.y += v2.y; acc.z += v2.z; acc.w += v2.w; }
            if (rem > 3) { acc.x += v3.x; acc.y += v3.y; acc.z += v3.z; acc.w += v3.w; }
        }
    } else {
        for (int e = 0; e < N_EDGES; e++) {          // ~never taken
            if (__ldg(ei + N_EDGES + e) == node) {
                float4 v = __ldg(x4 + (size_t)__ldg(ei + e) * 16 + j);
                acc.x += v.x; acc.y += v.y; acc.z += v.z; acc.w += v.w;
            }
        }
    }
    acc.x *= r; acc.y *= r; acc.z *= r; acc.w *= r;
    reinterpret_cast<float4*>(g_mean)[(size_t)node * 16 + j] = acc;
}

// ---------------------------------------------------------------------------
// Kernel 3: warp-level tf32 tensor-core GEMM (mma.sync m16n8k8) —
// ROUND-15 FORM VERBATIM (measured 46.7us; packed-B variant spilled regs).
// out[128n x 64o] = relu([mean|x] @ [Wl|Wr]^T + b), K = 128.
// 3-pass tf32 split (hh + hl + lh) for fp32 accuracy (~1e-7).
// ---------------------------------------------------------------------------
#define BSTRIDE 132

__device__ __forceinline__ uint32_t cvt_tf32(float f) {
    uint32_t r; asm("cvt.rna.tf32.f32 %0, %1;" : "=r"(r) : "f"(f)); return r;
}
__device__ __forceinline__ void mma_tf32(float c[4],
                                         uint32_t a0, uint32_t a1, uint32_t a2, uint32_t a3,
                                         uint32_t b0, uint32_t b1) {
    asm volatile(
        "mma.sync.aligned.m16n8k8.row.col.f32.tf32.tf32.f32 "
        "{%0,%1,%2,%3}, {%4,%5,%6,%7}, {%8,%9}, {%0,%1,%2,%3};"
        : "+f"(c[0]), "+f"(c[1]), "+f"(c[2]), "+f"(c[3])
        : "r"(a0), "r"(a1), "r"(a2), "r"(a3), "r"(b0), "r"(b1));
}

__global__ __launch_bounds__(256, 2) void mma_kernel(
    const float* __restrict__ x,
    const float* __restrict__ Wl,
    const float* __restrict__ bl,
    const float* __restrict__ Wr,
    float* __restrict__ out)
{
    extern __shared__ uint32_t smw[];
    uint32_t* sBhi = smw;                     // [64][BSTRIDE] tf32 hi
    uint32_t* sBlo = smw + 64 * BSTRIDE;      // [64][BSTRIDE] tf32 lo

    const int tid  = threadIdx.x;
    const int wid  = tid >> 5;                // 0..7
    const int lane = tid & 31;
    const int grp  = lane >> 2;               // groupID 0..7
    const int tid4 = lane & 3;                // threadID_in_group
    const int node0 = blockIdx.x * 128;

    // --- stage B = [Wl | Wr] as tf32 hi/lo planes, [o][k] k 0..127 ---
    for (int idx = tid; idx < 64 * 32; idx += 256) {
        const int o = idx >> 5;               // 0..63
        const int q = idx & 31;               // float4 index along k (k = q*4)
        const float4 v = (q < 16)
            ? __ldg(reinterpret_cast<const float4*>(Wl) + o * 16 + q)
            : __ldg(reinterpret_cast<const float4*>(Wr) + o * 16 + (q - 16));
        uint32_t h0 = cvt_tf32(v.x), h1 = cvt_tf32(v.y), h2 = cvt_tf32(v.z), h3 = cvt_tf32(v.w);
        uint32_t l0 = cvt_tf32(v.x - __uint_as_float(h0));
        uint32_t l1 = cvt_tf32(v.y - __uint_as_float(h1));
        uint32_t l2 = cvt_tf32(v.z - __uint_as_float(h2));
        uint32_t l3 = cvt_tf32(v.w - __uint_as_float(h3));
        const int base = o * BSTRIDE + q * 4;      // 16B-aligned (132 % 4 == 0)
        asm volatile("st.shared.v4.b32 [%0], {%1,%2,%3,%4};"
                     :: "r"((uint32_t)__cvta_generic_to_shared(sBhi + base)),
                        "r"(h0), "r"(h1), "r"(h2), "r"(h3) : "memory");
        asm volatile("st.shared.v4.b32 [%0], {%1,%2,%3,%4};"
                     :: "r"((uint32_t)__cvta_generic_to_shared(sBlo + base)),
                        "r"(l0), "r"(l1), "r"(l2), "r"(l3) : "memory");
    }
    __syncthreads();

    // --- A row offsets for this thread's fragments (clamped for tail CTA) ---
    const int r0 = node0 + wid * 16 + grp;
    const int r1 = r0 + 8;
    const size_t off0 = (size_t)(r0 < N_NODES ? r0 : N_NODES - 1) * D;
    const size_t off1 = (size_t)(r1 < N_NODES ? r1 : N_NODES - 1) * D;

    float c[8][4];
    #pragma unroll
    for (int nt = 0; nt < 8; nt++)
        #pragma unroll
        for (int i = 0; i < 4; i++) c[nt][i] = 0.f;

    // --- mainloop: 16 k-steps of 8 (s<8 -> mean/Wl half, s>=8 -> x/Wr half) ---
    #pragma unroll 2
    for (int s = 0; s < 16; s++) {
        const float* As = (s < 8) ? g_mean : x;
        const int kk = (s & 7) * 8;
        const float va0 = __ldg(As + off0 + kk + tid4);
        const float va1 = __ldg(As + off1 + kk + tid4);
        const float va2 = __ldg(As + off0 + kk + tid4 + 4);
        const float va3 = __ldg(As + off1 + kk + tid4 + 4);
        const uint32_t ah0 = cvt_tf32(va0), ah1 = cvt_tf32(va1);
        const uint32_t ah2 = cvt_tf32(va2), ah3 = cvt_tf32(va3);
        const uint32_t al0 = cvt_tf32(va0 - __uint_as_float(ah0));
        const uint32_t al1 = cvt_tf32(va1 - __uint_as_float(ah1));
        const uint32_t al2 = cvt_tf32(va2 - __uint_as_float(ah2));
        const uint32_t al3 = cvt_tf32(va3 - __uint_as_float(ah3));

        const int bcol = s * 8 + tid4;             // global k for B fragments
        #pragma unroll
        for (int nt = 0; nt < 8; nt++) {
            const int bb = (nt * 8 + grp) * BSTRIDE + bcol;
            const uint32_t bh0 = sBhi[bb], bh1 = sBhi[bb + 4];
            const uint32_t bl0 = sBlo[bb], bl1 = sBlo[bb + 4];
            mma_tf32(c[nt], ah0, ah1, ah2, ah3, bh0, bh1);   // hi*hi
            mma_tf32(c[nt], ah0, ah1, ah2, ah3, bl0, bl1);   // hi*lo
            mma_tf32(c[nt], al0, al1, al2, al3, bh0, bh1);   // lo*hi
        }
    }

    // --- epilogue: +bias, ReLU, store float2 pairs ---
    const int colb = 2 * tid4;
    #pragma unroll
    for (int nt = 0; nt < 8; nt++) {
        const int col = nt * 8 + colb;
        const float2 b2 = __ldg(reinterpret_cast<const float2*>(bl + col));
        if (r0 < N_NODES) {
            float2 v;
            v.x = fmaxf(c[nt][0] + b2.x, 0.f);
            v.y = fmaxf(c[nt][1] + b2.y, 0.f);
            *reinterpret_cast<float2*>(out + (size_t)r0 * D + col) = v;
        }
        if (r1 < N_NODES) {
            float2 v;
            v.x = fmaxf(c[nt][2] + b2.x, 0.f);
            v.y = fmaxf(c[nt][3] + b2.y, 0.f);
            *reinterpret_cast<float2*>(out + (size_t)r1 * D + col) = v;
        }
    }
}

// ---------------------------------------------------------------------------
extern "C" void kernel_launch(void* const* d_in, const int* in_sizes, int n_in,
                              void* d_out, int out_size)
{
    const float* x  = (const float*)d_in[0];
    const int*   ei = (const int*)d_in[1];     // int32 (JAX x64 disabled)
    const float* Wl = (const float*)d_in[2];
    const float* bl = (const float*)d_in[3];
    const float* Wr = (const float*)d_in[4];
    float* out = (float*)d_out;

    const int smem_bytes = 2 * 64 * BSTRIDE * sizeof(uint32_t);   // 67.6 KB
    cudaFuncSetAttribute(mma_kernel, cudaFuncAttributeMaxDynamicSharedMemorySize, smem_bytes);

    fill_kernel<<<(EQ + 255) / 256, 256>>>(ei);
    gather_kernel<<<N_NODES / 16, 256>>>(x, ei);   // 2 nodes/warp * 8 warps
    mma_kernel<<<(N_NODES + 127) / 128, 256, smem_bytes>>>(x, Wl, bl, Wr, out);
}